// round 2
// baseline (speedup 1.0000x reference)
#include <cuda_runtime.h>
#include <math.h>

#define BATCH 16
#define SEQ 1024
#define IN_DIM 310
#define E 64
#define NH 8
#define HD 8
#define ROWS (BATCH*SEQ)          // 16384
#define WIN 5
#define NKEYS 342                 // #{j < 1024 : j%3==0}
#define SCALE 0.35355339059327373f  // 1/sqrt(8)

// ---------------- scratch (static device memory; no allocation) ----------------
__device__ float g_xp[ROWS*E];                 // projected input [row][64]
__device__ float g_q[2][BATCH*NH*SEQ*HD];      // [attn][b*NH+h][s][d]
__device__ float g_k[2][BATCH*NH*SEQ*HD];
__device__ float g_v[2][BATCH*NH*SEQ*HD];
__device__ float g_o[2][ROWS*E];               // attention out, head-concat layout
__device__ float g_M[2][E*E];                  // combined fusion matrices
__device__ float g_cb[E];                      // combined bias
__device__ float g_scores[ROWS];               // pooling logits
__device__ float g_fused[ROWS*E];              // fused features

// ---------------- tiny kernel: fold out-proj + fusion weights ----------------
__global__ void combine_w_kernel(const float* __restrict__ fw, const float* __restrict__ fb,
                                 const float* __restrict__ low, const float* __restrict__ lob,
                                 const float* __restrict__ gow, const float* __restrict__ gob) {
    int t = threadIdx.x;
    for (int idx = t; idx < E*E; idx += blockDim.x) {
        int e = idx / E, f = idx % E;
        float a = 0.f, b = 0.f;
        for (int g = 0; g < E; g++) {
            a = fmaf(fw[e*2*E + g],     low[g*E + f], a);
            b = fmaf(fw[e*2*E + E + g], gow[g*E + f], b);
        }
        g_M[0][idx] = a;
        g_M[1][idx] = b;
    }
    if (t < E) {
        float c = fb[t];
        for (int g = 0; g < E; g++) {
            c = fmaf(fw[t*2*E + g], lob[g], c);
            c = fmaf(fw[t*2*E + E + g], gob[g], c);
        }
        g_cb[t] = c;
    }
}

// ---------------- shared GEMM mainloop: C[64x64] tile, 4x4 per thread ----------------
// A: [M][lda] row-major, W: [N][ldw] row-major (C = A * W^T)
__device__ __forceinline__ void gemm_accum(
    float (&As)[16][68], float (&Ws)[16][68],
    const float* __restrict__ A, int lda,
    const float* __restrict__ W, int ldw,
    int row0, int wrow0, int Kdim,
    float* acc, int tid)
{
    int tc = tid & 15, tr = tid >> 4;
    for (int k0 = 0; k0 < Kdim; k0 += 16) {
        #pragma unroll
        for (int p = 0; p < 4; p++) {
            int i = tid + p * 256;
            int kk = i & 15, r = i >> 4;
            int k = k0 + kk;
            As[kk][r] = (k < Kdim) ? A[(size_t)(row0 + r) * lda + k] : 0.f;
            Ws[kk][r] = (k < Kdim) ? W[(size_t)(wrow0 + r) * ldw + k] : 0.f;
        }
        __syncthreads();
        #pragma unroll
        for (int kk = 0; kk < 16; kk++) {
            float4 av = *(const float4*)&As[kk][4*tr];
            float4 wv = *(const float4*)&Ws[kk][4*tc];
            float a4[4] = {av.x, av.y, av.z, av.w};
            float w4[4] = {wv.x, wv.y, wv.z, wv.w};
            #pragma unroll
            for (int i = 0; i < 4; i++)
                #pragma unroll
                for (int j = 0; j < 4; j++)
                    acc[i*4+j] = fmaf(a4[i], w4[j], acc[i*4+j]);
        }
        __syncthreads();
    }
}

// ---------------- input projection: g_xp = x @ proj_w^T + proj_b ----------------
__global__ void proj_kernel(const float* __restrict__ x,
                            const float* __restrict__ pw,
                            const float* __restrict__ pb) {
    __shared__ __align__(16) float As[16][68];
    __shared__ __align__(16) float Ws[16][68];
    int tid = threadIdx.x;
    int row0 = blockIdx.x * 64;
    float acc[16] = {0};
    gemm_accum(As, Ws, x, IN_DIM, pw, IN_DIM, row0, 0, IN_DIM, acc, tid);
    int tc = tid & 15, tr = tid >> 4;
    #pragma unroll
    for (int i = 0; i < 4; i++) {
        int row = row0 + 4*tr + i;
        float4 o;
        o.x = acc[i*4+0] + pb[4*tc+0];
        o.y = acc[i*4+1] + pb[4*tc+1];
        o.z = acc[i*4+2] + pb[4*tc+2];
        o.w = acc[i*4+3] + pb[4*tc+3];
        *(float4*)&g_xp[(size_t)row*E + 4*tc] = o;
    }
}

// ---------------- QKV projection, writes [b*NH+h][s][d] layout ----------------
__global__ void qkv_kernel(const float* __restrict__ w,
                           const float* __restrict__ bias,
                           int attn) {
    __shared__ __align__(16) float As[16][68];
    __shared__ __align__(16) float Ws[16][68];
    int tid = threadIdx.x;
    int row0 = blockIdx.x * 64;
    int which = blockIdx.y;  // 0=q,1=k,2=v
    float acc[16] = {0};
    gemm_accum(As, Ws, g_xp, E, w, E, row0, which*64, E, acc, tid);
    int tc = tid & 15, tr = tid >> 4;
    float* outp = (which == 0) ? g_q[attn] : (which == 1) ? g_k[attn] : g_v[attn];
    #pragma unroll
    for (int i = 0; i < 4; i++) {
        int row = row0 + 4*tr + i;
        int b = row >> 10, s = row & 1023;
        #pragma unroll
        for (int j = 0; j < 4; j++) {
            int c = 4*tc + j;
            int h = c >> 3, dd = c & 7;
            outp[(((size_t)(b*NH + h))*SEQ + s)*HD + dd] = acc[i*4+j] + bias[which*64 + c];
        }
    }
}

// ---------------- local attention: band |i-j|<=5, one thread per query ----------------
__global__ void local_attn_kernel() {
    int idx = blockIdx.x * blockDim.x + threadIdx.x;   // over BATCH*NH*SEQ
    int s = idx & (SEQ-1);
    int bh = idx >> 10;
    const float* qp = g_q[0] + (size_t)idx * HD;
    float4 qa = *(const float4*)qp;
    float4 qb = *(const float4*)(qp + 4);
    const float* kbase = g_k[0] + (size_t)bh * SEQ * HD;
    const float* vbase = g_v[0] + (size_t)bh * SEQ * HD;
    int jlo = (s - WIN < 0) ? 0 : s - WIN;
    int jhi = (s + WIN > SEQ-1) ? SEQ-1 : s + WIN;
    float m = -1e30f, l = 0.f;
    float acc[8] = {0,0,0,0,0,0,0,0};
    for (int j = jlo; j <= jhi; j++) {
        float4 ka = *(const float4*)(kbase + (size_t)j*HD);
        float4 kb = *(const float4*)(kbase + (size_t)j*HD + 4);
        float sc = qa.x*ka.x + qa.y*ka.y + qa.z*ka.z + qa.w*ka.w
                 + qb.x*kb.x + qb.y*kb.y + qb.z*kb.z + qb.w*kb.w;
        sc *= SCALE;
        float mn = fmaxf(m, sc);
        float corr = __expf(m - mn);
        float p = __expf(sc - mn);
        l = l * corr + p;
        float4 va = *(const float4*)(vbase + (size_t)j*HD);
        float4 vb = *(const float4*)(vbase + (size_t)j*HD + 4);
        acc[0] = acc[0]*corr + p*va.x;  acc[1] = acc[1]*corr + p*va.y;
        acc[2] = acc[2]*corr + p*va.z;  acc[3] = acc[3]*corr + p*va.w;
        acc[4] = acc[4]*corr + p*vb.x;  acc[5] = acc[5]*corr + p*vb.y;
        acc[6] = acc[6]*corr + p*vb.z;  acc[7] = acc[7]*corr + p*vb.w;
        m = mn;
    }
    float inv = 1.f / l;
    int b = bh >> 3, h = bh & 7;
    float* op = g_o[0] + ((size_t)(b*SEQ + s))*E + h*HD;
    float4 o0 = {acc[0]*inv, acc[1]*inv, acc[2]*inv, acc[3]*inv};
    float4 o1 = {acc[4]*inv, acc[5]*inv, acc[6]*inv, acc[7]*inv};
    *(float4*)op = o0;
    *(float4*)(op + 4) = o1;
}

// ---------------- sparse attention: keys j%3==0 (+ diagonal), K/V in smem ----------------
__global__ void sparse_attn_kernel() {
    __shared__ __align__(16) float Ks[NKEYS][8];
    __shared__ __align__(16) float Vs[NKEYS][8];
    int bh = blockIdx.x;                       // 0..127
    int s  = blockIdx.y * 128 + threadIdx.x;
    const float* kb = g_k[1] + (size_t)bh * SEQ * HD;
    const float* vb = g_v[1] + (size_t)bh * SEQ * HD;
    for (int i = threadIdx.x; i < NKEYS*8; i += 128) {
        int kk = i >> 3, dd = i & 7;
        Ks[kk][dd] = kb[kk*24 + dd];           // key row 3*kk
        Vs[kk][dd] = vb[kk*24 + dd];
    }
    __syncthreads();
    const float* qp = g_q[1] + ((size_t)bh * SEQ + s) * HD;
    float4 qa = *(const float4*)qp;
    float4 qb = *(const float4*)(qp + 4);
    float m = -1e30f, l = 0.f;
    float acc[8] = {0,0,0,0,0,0,0,0};
    for (int kk = 0; kk < NKEYS; kk++) {
        float4 ka = *(const float4*)&Ks[kk][0];
        float4 kb4 = *(const float4*)&Ks[kk][4];
        float sc = qa.x*ka.x + qa.y*ka.y + qa.z*ka.z + qa.w*ka.w
                 + qb.x*kb4.x + qb.y*kb4.y + qb.z*kb4.z + qb.w*kb4.w;
        sc *= SCALE;
        if (sc > m) {                          // rare rescale path
            float corr = __expf(m - sc);
            l *= corr;
            #pragma unroll
            for (int d2 = 0; d2 < 8; d2++) acc[d2] *= corr;
            m = sc;
        }
        float p = __expf(sc - m);
        l += p;
        float4 va = *(const float4*)&Vs[kk][0];
        float4 vb4 = *(const float4*)&Vs[kk][4];
        acc[0] = fmaf(p, va.x, acc[0]);  acc[1] = fmaf(p, va.y, acc[1]);
        acc[2] = fmaf(p, va.z, acc[2]);  acc[3] = fmaf(p, va.w, acc[3]);
        acc[4] = fmaf(p, vb4.x, acc[4]); acc[5] = fmaf(p, vb4.y, acc[5]);
        acc[6] = fmaf(p, vb4.z, acc[6]); acc[7] = fmaf(p, vb4.w, acc[7]);
    }
    if (s % 3) {                               // diagonal key not in the j%3 set
        const float* kp = kb + (size_t)s * HD;
        float4 ka = *(const float4*)kp;
        float4 kb4 = *(const float4*)(kp + 4);
        float sc = qa.x*ka.x + qa.y*ka.y + qa.z*ka.z + qa.w*ka.w
                 + qb.x*kb4.x + qb.y*kb4.y + qb.z*kb4.z + qb.w*kb4.w;
        sc *= SCALE;
        if (sc > m) {
            float corr = __expf(m - sc);
            l *= corr;
            #pragma unroll
            for (int d2 = 0; d2 < 8; d2++) acc[d2] *= corr;
            m = sc;
        }
        float p = __expf(sc - m);
        l += p;
        const float* vp = vb + (size_t)s * HD;
        float4 va = *(const float4*)vp;
        float4 vb4 = *(const float4*)(vp + 4);
        acc[0] = fmaf(p, va.x, acc[0]);  acc[1] = fmaf(p, va.y, acc[1]);
        acc[2] = fmaf(p, va.z, acc[2]);  acc[3] = fmaf(p, va.w, acc[3]);
        acc[4] = fmaf(p, vb4.x, acc[4]); acc[5] = fmaf(p, vb4.y, acc[5]);
        acc[6] = fmaf(p, vb4.z, acc[6]); acc[7] = fmaf(p, vb4.w, acc[7]);
    }
    float inv = 1.f / l;
    int b = bh >> 3, h = bh & 7;
    float* op = g_o[1] + ((size_t)(b*SEQ + s))*E + h*HD;
    float4 o0 = {acc[0]*inv, acc[1]*inv, acc[2]*inv, acc[3]*inv};
    float4 o1 = {acc[4]*inv, acc[5]*inv, acc[6]*inv, acc[7]*inv};
    *(float4*)op = o0;
    *(float4*)(op + 4) = o1;
}

// ---------------- fused = o_loc @ M_loc^T + o_glob @ M_glob^T + cb ----------------
__global__ void fused_kernel() {
    __shared__ __align__(16) float As[16][68];
    __shared__ __align__(16) float Ws[16][68];
    int tid = threadIdx.x;
    int row0 = blockIdx.x * 64;
    float acc[16] = {0};
    gemm_accum(As, Ws, g_o[0], E, g_M[0], E, row0, 0, E, acc, tid);
    gemm_accum(As, Ws, g_o[1], E, g_M[1], E, row0, 0, E, acc, tid);
    int tc = tid & 15, tr = tid >> 4;
    #pragma unroll
    for (int i = 0; i < 4; i++) {
        int row = row0 + 4*tr + i;
        float4 o;
        o.x = acc[i*4+0] + g_cb[4*tc+0];
        o.y = acc[i*4+1] + g_cb[4*tc+1];
        o.z = acc[i*4+2] + g_cb[4*tc+2];
        o.w = acc[i*4+3] + g_cb[4*tc+3];
        *(float4*)&g_fused[(size_t)row*E + 4*tc] = o;
    }
}

// ---------------- pooling logits: tanh(fused@w1^T+b1)@w2^T+b2 ----------------
__global__ void pool_score_kernel(const float* __restrict__ w1,
                                  const float* __restrict__ b1,
                                  const float* __restrict__ w2,
                                  const float* __restrict__ b2) {
    __shared__ float w1s[32][65];
    __shared__ float w2s[32], b1s[32];
    int tid = threadIdx.x;
    for (int i = tid; i < 32*64; i += blockDim.x)
        w1s[i >> 6][i & 63] = w1[i];
    if (tid < 32) { w2s[tid] = w2[tid]; b1s[tid] = b1[tid]; }
    __syncthreads();
    int warp = tid >> 5, lane = tid & 31;
    int row = blockIdx.x * 8 + warp;
    const float* fr = g_fused + (size_t)row * E;
    float f0 = fr[lane], f1 = fr[lane + 32];
    float h = 0.f;
    #pragma unroll
    for (int e = 0; e < 32; e++) {
        float v = __shfl_sync(0xffffffffu, f0, e);
        h = fmaf(v, w1s[lane][e], h);
    }
    #pragma unroll
    for (int e = 0; e < 32; e++) {
        float v = __shfl_sync(0xffffffffu, f1, e);
        h = fmaf(v, w1s[lane][e + 32], h);
    }
    h = tanhf(h + b1s[lane]);
    float p = h * w2s[lane];
    #pragma unroll
    for (int off = 16; off; off >>= 1)
        p += __shfl_xor_sync(0xffffffffu, p, off);
    if (lane == 0) g_scores[row] = p + b2[0];
}

// ---------------- softmax over seq + weighted sum -> out[b][e] ----------------
__global__ void pool_out_kernel(float* __restrict__ out) {
    int b = blockIdx.x;
    int tid = threadIdx.x;  // 256
    __shared__ float ws[SEQ];
    __shared__ float red[8];
    __shared__ float s_max, s_sum;
    __shared__ float part[4][64];
    const float* sc = g_scores + (size_t)b * SEQ;
    float m = -1e30f;
    for (int i = tid; i < SEQ; i += 256) m = fmaxf(m, sc[i]);
    #pragma unroll
    for (int off = 16; off; off >>= 1) m = fmaxf(m, __shfl_xor_sync(0xffffffffu, m, off));
    if ((tid & 31) == 0) red[tid >> 5] = m;
    __syncthreads();
    if (tid == 0) {
        float mm = red[0];
        for (int i = 1; i < 8; i++) mm = fmaxf(mm, red[i]);
        s_max = mm;
    }
    __syncthreads();
    float mm = s_max;
    float lsum = 0.f;
    for (int i = tid; i < SEQ; i += 256) {
        float e = __expf(sc[i] - mm);
        ws[i] = e;
        lsum += e;
    }
    #pragma unroll
    for (int off = 16; off; off >>= 1) lsum += __shfl_xor_sync(0xffffffffu, lsum, off);
    __syncthreads();          // red[] reuse guard
    if ((tid & 31) == 0) red[tid >> 5] = lsum;
    __syncthreads();
    if (tid == 0) {
        float ss = 0.f;
        for (int i = 0; i < 8; i++) ss += red[i];
        s_sum = ss;
    }
    __syncthreads();
    int e = tid & 63, g = tid >> 6;
    const float* fb = g_fused + (size_t)b * SEQ * E;
    float a = 0.f;
    for (int s = g*256; s < g*256 + 256; s++)
        a = fmaf(ws[s], fb[(size_t)s*E + e], a);
    part[g][e] = a;
    __syncthreads();
    if (tid < 64)
        out[b*64 + tid] = (part[0][tid] + part[1][tid] + part[2][tid] + part[3][tid]) / s_sum;
}

// ---------------- launch ----------------
extern "C" void kernel_launch(void* const* d_in, const int* in_sizes, int n_in,
                              void* d_out, int out_size) {
    const float* x        = (const float*)d_in[0];
    const float* proj_w   = (const float*)d_in[1];
    const float* proj_b   = (const float*)d_in[2];
    const float* loc_in_w = (const float*)d_in[3];
    const float* loc_in_b = (const float*)d_in[4];
    const float* loc_out_w= (const float*)d_in[5];
    const float* loc_out_b= (const float*)d_in[6];
    const float* glb_in_w = (const float*)d_in[7];
    const float* glb_in_b = (const float*)d_in[8];
    const float* glb_out_w= (const float*)d_in[9];
    const float* glb_out_b= (const float*)d_in[10];
    const float* fusion_w = (const float*)d_in[11];
    const float* fusion_b = (const float*)d_in[12];
    const float* pool_w1  = (const float*)d_in[13];
    const float* pool_b1  = (const float*)d_in[14];
    const float* pool_w2  = (const float*)d_in[15];
    const float* pool_b2  = (const float*)d_in[16];
    float* out = (float*)d_out;

    combine_w_kernel<<<1, 256>>>(fusion_w, fusion_b, loc_out_w, loc_out_b,
                                 glb_out_w, glb_out_b);
    proj_kernel<<<ROWS/64, 256>>>(x, proj_w, proj_b);
    qkv_kernel<<<dim3(ROWS/64, 3), 256>>>(loc_in_w, loc_in_b, 0);
    qkv_kernel<<<dim3(ROWS/64, 3), 256>>>(glb_in_w, glb_in_b, 1);
    local_attn_kernel<<<(BATCH*NH*SEQ)/256, 256>>>();
    sparse_attn_kernel<<<dim3(BATCH*NH, SEQ/128), 128>>>();
    fused_kernel<<<ROWS/64, 256>>>();
    pool_score_kernel<<<ROWS/8, 256>>>(pool_w1, pool_b1, pool_w2, pool_b2);
    pool_out_kernel<<<BATCH, 256>>>(out);
}

// round 3
// speedup vs baseline: 1.3132x; 1.3132x over previous
#include <cuda_runtime.h>
#include <math.h>

#define BATCH 16
#define SEQ 1024
#define IN_DIM 310
#define E 64
#define NH 8
#define HD 8
#define ROWS (BATCH*SEQ)          // 16384
#define WIN 5
#define NKEYS 342                 // #{j < 1024 : j%3==0}
#define SCALE 0.35355339059327373f  // 1/sqrt(8)

typedef unsigned long long ull;

// ---------------- f32x2 packed helpers ----------------
__device__ __forceinline__ ull pk2(float lo, float hi) {
    ull r; asm("mov.b64 %0,{%1,%2};" : "=l"(r) : "f"(lo), "f"(hi)); return r;
}
__device__ __forceinline__ void upk2(ull v, float& lo, float& hi) {
    asm("mov.b64 {%0,%1},%2;" : "=f"(lo), "=f"(hi) : "l"(v));
}
__device__ __forceinline__ ull ffma2(ull a, ull b, ull c) {
    ull d; asm("fma.rn.f32x2 %0,%1,%2,%3;" : "=l"(d) : "l"(a), "l"(b), "l"(c)); return d;
}
__device__ __forceinline__ ull fmul2(ull a, ull b) {
    ull d; asm("mul.rn.f32x2 %0,%1,%2;" : "=l"(d) : "l"(a), "l"(b)); return d;
}

// ---------------- scratch (static device memory; no allocation) ----------------
__device__ float g_xp[ROWS*E];                 // projected input [row][64]
__device__ float g_q[2][BATCH*NH*SEQ*HD];      // [attn][b*NH+h][s][d]
__device__ float g_k[2][BATCH*NH*SEQ*HD];
__device__ float g_v[2][BATCH*NH*SEQ*HD];
__device__ float g_o[2][ROWS*E];               // attention out, head-concat layout
__device__ float g_M[2][E*E];                  // combined fusion matrices
__device__ float g_cb[E];                      // combined bias
__device__ float g_scores[ROWS];               // pooling logits
__device__ float g_fused[ROWS*E];              // fused features

// ---------------- fold out-proj + fusion weights (wide grid) ----------------
__global__ void combine_w_kernel(const float* __restrict__ fw, const float* __restrict__ fb,
                                 const float* __restrict__ low, const float* __restrict__ lob,
                                 const float* __restrict__ gow, const float* __restrict__ gob) {
    int idx = blockIdx.x * 64 + threadIdx.x;   // 0..4095
    int e = idx >> 6, f = idx & 63;
    float a = 0.f, b = 0.f;
    #pragma unroll 4
    for (int g = 0; g < E; g++) {
        a = fmaf(fw[e*2*E + g],     low[g*E + f], a);
        b = fmaf(fw[e*2*E + E + g], gow[g*E + f], b);
    }
    g_M[0][idx] = a;
    g_M[1][idx] = b;
    if (idx < E) {
        float c = fb[idx];
        for (int g = 0; g < E; g++) {
            c = fmaf(fw[idx*2*E + g], lob[g], c);
            c = fmaf(fw[idx*2*E + E + g], gob[g], c);
        }
        g_cb[idx] = c;
    }
}

// ---------------- GEMM tile: 128 rows x 64 cols per block, 256 threads ----------------
// microtile: 8 rows (as 4 f32x2 pairs) x 4 cols. C = A @ W^T
struct GemmSmem {
    float As[16][132];   // [kk][row], padded: stride 132 (16B-aligned, low conflict)
    float Ws[16][68];    // [kk][col]
};

__device__ __forceinline__ void gemm_tile(
    GemmSmem& sm,
    const float* __restrict__ A, int lda, int row0,
    const float* __restrict__ W, int ldw, int wrow0,
    int Kdim, ull (&acc)[4][4], int tid)
{
    int tc = tid & 15, tr = tid >> 4;
    for (int k0 = 0; k0 < Kdim; k0 += 16) {
        #pragma unroll
        for (int p = 0; p < 8; p++) {          // A panel: 128x16
            int i = tid + p * 256;
            int kk = i & 15, r = i >> 4;
            int k = k0 + kk;
            sm.As[kk][r] = (k < Kdim) ? A[(size_t)(row0 + r) * lda + k] : 0.f;
        }
        #pragma unroll
        for (int p = 0; p < 4; p++) {          // W panel: 64x16
            int i = tid + p * 256;
            int kk = i & 15, c = i >> 4;
            int k = k0 + kk;
            sm.Ws[kk][c] = (k < Kdim) ? W[(size_t)(wrow0 + c) * ldw + k] : 0.f;
        }
        __syncthreads();
        #pragma unroll
        for (int kk = 0; kk < 16; kk++) {
            ulonglong2 a01 = *(const ulonglong2*)&sm.As[kk][8*tr];
            ulonglong2 a23 = *(const ulonglong2*)&sm.As[kk][8*tr + 4];
            float4 wv = *(const float4*)&sm.Ws[kk][4*tc];
            ull ap[4] = {a01.x, a01.y, a23.x, a23.y};
            ull w2[4] = {pk2(wv.x, wv.x), pk2(wv.y, wv.y), pk2(wv.z, wv.z), pk2(wv.w, wv.w)};
            #pragma unroll
            for (int p = 0; p < 4; p++)
                #pragma unroll
                for (int j = 0; j < 4; j++)
                    acc[p][j] = ffma2(ap[p], w2[j], acc[p][j]);
        }
        __syncthreads();
    }
}

__device__ __forceinline__ void unpack_acc(ull (&acc)[4][4], float (&o)[8][4]) {
    #pragma unroll
    for (int p = 0; p < 4; p++)
        #pragma unroll
        for (int j = 0; j < 4; j++)
            upk2(acc[p][j], o[2*p][j], o[2*p+1][j]);
}

// ---------------- input projection: g_xp = x @ proj_w^T + proj_b ----------------
__global__ __launch_bounds__(256) void proj_kernel(const float* __restrict__ x,
                            const float* __restrict__ pw,
                            const float* __restrict__ pb) {
    __shared__ GemmSmem sm;
    int tid = threadIdx.x;
    int row0 = blockIdx.x * 128;
    ull acc[4][4] = {};
    gemm_tile(sm, x, IN_DIM, row0, pw, IN_DIM, 0, IN_DIM, acc, tid);
    int tc = tid & 15, tr = tid >> 4;
    float o[8][4];
    unpack_acc(acc, o);
    float4 bias = *(const float4*)&pb[4*tc];
    #pragma unroll
    for (int i = 0; i < 8; i++) {
        int row = row0 + 8*tr + i;
        float4 v = {o[i][0] + bias.x, o[i][1] + bias.y, o[i][2] + bias.z, o[i][3] + bias.w};
        *(float4*)&g_xp[(size_t)row*E + 4*tc] = v;
    }
}

// ---------------- QKV projection for BOTH attentions in one launch ----------------
__global__ __launch_bounds__(256) void qkv_kernel(const float* __restrict__ loc_w,
                           const float* __restrict__ loc_b,
                           const float* __restrict__ glb_w,
                           const float* __restrict__ glb_b) {
    __shared__ GemmSmem sm;
    int tid = threadIdx.x;
    int row0 = blockIdx.x * 128;
    int y = blockIdx.y;          // 0..5
    int attn = y / 3, which = y % 3;
    const float* w    = attn ? glb_w : loc_w;
    const float* bias = attn ? glb_b : loc_b;
    ull acc[4][4] = {};
    gemm_tile(sm, g_xp, E, row0, w, E, which*64, E, acc, tid);
    int tc = tid & 15, tr = tid >> 4;
    float o[8][4];
    unpack_acc(acc, o);
    float* outp = (which == 0) ? g_q[attn] : (which == 1) ? g_k[attn] : g_v[attn];
    int c = 4*tc;                 // 4 cols all inside one head: dd in {0,4}
    int h = c >> 3, dd = c & 7;
    float4 bv = *(const float4*)&bias[which*64 + c];
    #pragma unroll
    for (int i = 0; i < 8; i++) {
        int row = row0 + 8*tr + i;
        int b = row >> 10, s = row & 1023;
        float4 v = {o[i][0] + bv.x, o[i][1] + bv.y, o[i][2] + bv.z, o[i][3] + bv.w};
        *(float4*)&outp[(((size_t)(b*NH + h))*SEQ + s)*HD + dd] = v;
    }
}

// ---------------- local attention: band |i-j|<=5 ----------------
// scores are O(1) -> direct exp is exact softmax, no running max needed
__global__ void local_attn_kernel() {
    int idx = blockIdx.x * blockDim.x + threadIdx.x;
    int s = idx & (SEQ-1);
    int bh = idx >> 10;
    const ull* qp = (const ull*)(g_q[0] + (size_t)idx * HD);
    ull q0 = qp[0], q1 = qp[1], q2 = qp[2], q3 = qp[3];
    const float* kbase = g_k[0] + (size_t)bh * SEQ * HD;
    const float* vbase = g_v[0] + (size_t)bh * SEQ * HD;
    int jlo = (s - WIN < 0) ? 0 : s - WIN;
    int jhi = (s + WIN > SEQ-1) ? SEQ-1 : s + WIN;
    float l = 0.f;
    ull acc[4] = {0,0,0,0};
    for (int j = jlo; j <= jhi; j++) {
        const ull* kp = (const ull*)(kbase + (size_t)j*HD);
        ull d2 = ffma2(q0, kp[0], ffma2(q1, kp[1], ffma2(q2, kp[2], fmul2(q3, kp[3]))));
        float dl, dh; upk2(d2, dl, dh);
        float p = __expf((dl + dh) * SCALE);
        l += p;
        ull pp = pk2(p, p);
        const ull* vp = (const ull*)(vbase + (size_t)j*HD);
        acc[0] = ffma2(pp, vp[0], acc[0]);
        acc[1] = ffma2(pp, vp[1], acc[1]);
        acc[2] = ffma2(pp, vp[2], acc[2]);
        acc[3] = ffma2(pp, vp[3], acc[3]);
    }
    float inv = 1.f / l;
    float oo[8];
    upk2(acc[0], oo[0], oo[1]); upk2(acc[1], oo[2], oo[3]);
    upk2(acc[2], oo[4], oo[5]); upk2(acc[3], oo[6], oo[7]);
    int b = bh >> 3, h = bh & 7;
    float* op = g_o[0] + ((size_t)(b*SEQ + s))*E + h*HD;
    float4 o0 = {oo[0]*inv, oo[1]*inv, oo[2]*inv, oo[3]*inv};
    float4 o1 = {oo[4]*inv, oo[5]*inv, oo[6]*inv, oo[7]*inv};
    *(float4*)op = o0;
    *(float4*)(op + 4) = o1;
}

// ---------------- sparse attention: keys j%3==0 (+ diagonal), K/V in smem ----------------
__global__ void sparse_attn_kernel() {
    __shared__ __align__(16) float Ks[NKEYS][8];
    __shared__ __align__(16) float Vs[NKEYS][8];
    int bh = blockIdx.x;
    int s  = blockIdx.y * 128 + threadIdx.x;
    const float* kb = g_k[1] + (size_t)bh * SEQ * HD;
    const float* vb = g_v[1] + (size_t)bh * SEQ * HD;
    for (int i = threadIdx.x; i < NKEYS*8; i += 128) {
        int kk = i >> 3, dd = i & 7;
        Ks[kk][dd] = kb[kk*24 + dd];           // key row 3*kk
        Vs[kk][dd] = vb[kk*24 + dd];
    }
    __syncthreads();
    const ull* qp = (const ull*)(g_q[1] + ((size_t)bh * SEQ + s) * HD);
    ull q0 = qp[0], q1 = qp[1], q2 = qp[2], q3 = qp[3];
    float l = 0.f;
    ull acc[4] = {0,0,0,0};
    #pragma unroll 2
    for (int kk = 0; kk < NKEYS; kk++) {
        const ull* kp = (const ull*)&Ks[kk][0];
        ull d2 = ffma2(q0, kp[0], ffma2(q1, kp[1], ffma2(q2, kp[2], fmul2(q3, kp[3]))));
        float dl, dh; upk2(d2, dl, dh);
        float p = __expf((dl + dh) * SCALE);
        l += p;
        ull pp = pk2(p, p);
        const ull* vp = (const ull*)&Vs[kk][0];
        acc[0] = ffma2(pp, vp[0], acc[0]);
        acc[1] = ffma2(pp, vp[1], acc[1]);
        acc[2] = ffma2(pp, vp[2], acc[2]);
        acc[3] = ffma2(pp, vp[3], acc[3]);
    }
    if (s % 3) {                               // diagonal key not in the j%3 set
        const ull* kp = (const ull*)(kb + (size_t)s * HD);
        ull d2 = ffma2(q0, kp[0], ffma2(q1, kp[1], ffma2(q2, kp[2], fmul2(q3, kp[3]))));
        float dl, dh; upk2(d2, dl, dh);
        float p = __expf((dl + dh) * SCALE);
        l += p;
        ull pp = pk2(p, p);
        const ull* vp = (const ull*)(vb + (size_t)s * HD);
        acc[0] = ffma2(pp, vp[0], acc[0]);
        acc[1] = ffma2(pp, vp[1], acc[1]);
        acc[2] = ffma2(pp, vp[2], acc[2]);
        acc[3] = ffma2(pp, vp[3], acc[3]);
    }
    float inv = 1.f / l;
    float oo[8];
    upk2(acc[0], oo[0], oo[1]); upk2(acc[1], oo[2], oo[3]);
    upk2(acc[2], oo[4], oo[5]); upk2(acc[3], oo[6], oo[7]);
    int b = bh >> 3, h = bh & 7;
    float* op = g_o[1] + ((size_t)(b*SEQ + s))*E + h*HD;
    float4 o0 = {oo[0]*inv, oo[1]*inv, oo[2]*inv, oo[3]*inv};
    float4 o1 = {oo[4]*inv, oo[5]*inv, oo[6]*inv, oo[7]*inv};
    *(float4*)op = o0;
    *(float4*)(op + 4) = o1;
}

// ---------------- fused = o_loc @ M_loc^T + o_glob @ M_glob^T + cb ----------------
__global__ __launch_bounds__(256) void fused_kernel() {
    __shared__ GemmSmem sm;
    int tid = threadIdx.x;
    int row0 = blockIdx.x * 128;
    ull acc[4][4] = {};
    gemm_tile(sm, g_o[0], E, row0, g_M[0], E, 0, E, acc, tid);
    gemm_tile(sm, g_o[1], E, row0, g_M[1], E, 0, E, acc, tid);
    int tc = tid & 15, tr = tid >> 4;
    float o[8][4];
    unpack_acc(acc, o);
    float4 bias = *(const float4*)&g_cb[4*tc];
    #pragma unroll
    for (int i = 0; i < 8; i++) {
        int row = row0 + 8*tr + i;
        float4 v = {o[i][0] + bias.x, o[i][1] + bias.y, o[i][2] + bias.z, o[i][3] + bias.w};
        *(float4*)&g_fused[(size_t)row*E + 4*tc] = v;
    }
}

// ---------------- pooling logits: tanh(fused@w1^T+b1)@w2^T+b2 ----------------
__global__ void pool_score_kernel(const float* __restrict__ w1,
                                  const float* __restrict__ b1,
                                  const float* __restrict__ w2,
                                  const float* __restrict__ b2) {
    __shared__ float w1s[32][65];
    __shared__ float w2s[32], b1s[32];
    int tid = threadIdx.x;
    for (int i = tid; i < 32*64; i += blockDim.x)
        w1s[i >> 6][i & 63] = w1[i];
    if (tid < 32) { w2s[tid] = w2[tid]; b1s[tid] = b1[tid]; }
    __syncthreads();
    int warp = tid >> 5, lane = tid & 31;
    int row = blockIdx.x * 8 + warp;
    const float* fr = g_fused + (size_t)row * E;
    float f0 = fr[lane], f1 = fr[lane + 32];
    float h = 0.f;
    #pragma unroll
    for (int e = 0; e < 32; e++) {
        float v = __shfl_sync(0xffffffffu, f0, e);
        h = fmaf(v, w1s[lane][e], h);
    }
    #pragma unroll
    for (int e = 0; e < 32; e++) {
        float v = __shfl_sync(0xffffffffu, f1, e);
        h = fmaf(v, w1s[lane][e + 32], h);
    }
    h = tanhf(h + b1s[lane]);
    float p = h * w2s[lane];
    #pragma unroll
    for (int off = 16; off; off >>= 1)
        p += __shfl_xor_sync(0xffffffffu, p, off);
    if (lane == 0) g_scores[row] = p + b2[0];
}

// ---------------- softmax over seq + weighted sum -> out[b][e] ----------------
__global__ void pool_out_kernel(float* __restrict__ out) {
    int b = blockIdx.x;
    int tid = threadIdx.x;  // 256
    __shared__ float ws[SEQ];
    __shared__ float red[8];
    __shared__ float s_max, s_sum;
    __shared__ float part[4][64];
    const float* sc = g_scores + (size_t)b * SEQ;
    float m = -1e30f;
    for (int i = tid; i < SEQ; i += 256) m = fmaxf(m, sc[i]);
    #pragma unroll
    for (int off = 16; off; off >>= 1) m = fmaxf(m, __shfl_xor_sync(0xffffffffu, m, off));
    if ((tid & 31) == 0) red[tid >> 5] = m;
    __syncthreads();
    if (tid == 0) {
        float mm = red[0];
        for (int i = 1; i < 8; i++) mm = fmaxf(mm, red[i]);
        s_max = mm;
    }
    __syncthreads();
    float mm = s_max;
    float lsum = 0.f;
    for (int i = tid; i < SEQ; i += 256) {
        float e = __expf(sc[i] - mm);
        ws[i] = e;
        lsum += e;
    }
    #pragma unroll
    for (int off = 16; off; off >>= 1) lsum += __shfl_xor_sync(0xffffffffu, lsum, off);
    __syncthreads();
    if ((tid & 31) == 0) red[tid >> 5] = lsum;
    __syncthreads();
    if (tid == 0) {
        float ss = 0.f;
        for (int i = 0; i < 8; i++) ss += red[i];
        s_sum = ss;
    }
    __syncthreads();
    int e = tid & 63, g = tid >> 6;
    const float* fb = g_fused + (size_t)b * SEQ * E;
    float a = 0.f;
    for (int s = g*256; s < g*256 + 256; s++)
        a = fmaf(ws[s], fb[(size_t)s*E + e], a);
    part[g][e] = a;
    __syncthreads();
    if (tid < 64)
        out[b*64 + tid] = (part[0][tid] + part[1][tid] + part[2][tid] + part[3][tid]) / s_sum;
}

// ---------------- launch ----------------
extern "C" void kernel_launch(void* const* d_in, const int* in_sizes, int n_in,
                              void* d_out, int out_size) {
    const float* x        = (const float*)d_in[0];
    const float* proj_w   = (const float*)d_in[1];
    const float* proj_b   = (const float*)d_in[2];
    const float* loc_in_w = (const float*)d_in[3];
    const float* loc_in_b = (const float*)d_in[4];
    const float* loc_out_w= (const float*)d_in[5];
    const float* loc_out_b= (const float*)d_in[6];
    const float* glb_in_w = (const float*)d_in[7];
    const float* glb_in_b = (const float*)d_in[8];
    const float* glb_out_w= (const float*)d_in[9];
    const float* glb_out_b= (const float*)d_in[10];
    const float* fusion_w = (const float*)d_in[11];
    const float* fusion_b = (const float*)d_in[12];
    const float* pool_w1  = (const float*)d_in[13];
    const float* pool_b1  = (const float*)d_in[14];
    const float* pool_w2  = (const float*)d_in[15];
    const float* pool_b2  = (const float*)d_in[16];
    float* out = (float*)d_out;

    combine_w_kernel<<<64, 64>>>(fusion_w, fusion_b, loc_out_w, loc_out_b,
                                 glb_out_w, glb_out_b);
    proj_kernel<<<ROWS/128, 256>>>(x, proj_w, proj_b);
    qkv_kernel<<<dim3(ROWS/128, 6), 256>>>(loc_in_w, loc_in_b, glb_in_w, glb_in_b);
    local_attn_kernel<<<(BATCH*NH*SEQ)/256, 256>>>();
    sparse_attn_kernel<<<dim3(BATCH*NH, SEQ/128), 128>>>();
    fused_kernel<<<ROWS/128, 256>>>();
    pool_score_kernel<<<ROWS/8, 256>>>(pool_w1, pool_b1, pool_w2, pool_b2);
    pool_out_kernel<<<BATCH, 256>>>(out);
}

// round 4
// speedup vs baseline: 1.5125x; 1.1517x over previous
#include <cuda_runtime.h>
#include <math.h>

#define BATCH 16
#define SEQ 1024
#define IN_DIM 310
#define E 64
#define NH 8
#define HD 8
#define ROWS (BATCH*SEQ)          // 16384
#define WIN 5
#define NKEYS 342                 // #{j < 1024 : j%3==0}
#define SCALE 0.35355339059327373f  // 1/sqrt(8)

typedef unsigned long long ull;

// ---------------- f32x2 packed helpers ----------------
__device__ __forceinline__ ull pk2(float lo, float hi) {
    ull r; asm("mov.b64 %0,{%1,%2};" : "=l"(r) : "f"(lo), "f"(hi)); return r;
}
__device__ __forceinline__ void upk2(ull v, float& lo, float& hi) {
    asm("mov.b64 {%0,%1},%2;" : "=f"(lo), "=f"(hi) : "l"(v));
}
__device__ __forceinline__ ull ffma2(ull a, ull b, ull c) {
    ull d; asm("fma.rn.f32x2 %0,%1,%2,%3;" : "=l"(d) : "l"(a), "l"(b), "l"(c)); return d;
}
__device__ __forceinline__ ull fmul2(ull a, ull b) {
    ull d; asm("mul.rn.f32x2 %0,%1,%2;" : "=l"(d) : "l"(a), "l"(b)); return d;
}

// ---------------- scratch (static device memory; no allocation) ----------------
__device__ float g_xp[ROWS*E];                 // projected input [row][64]
__device__ float g_q[2][BATCH*NH*SEQ*HD];      // [attn][b*NH+h][s][d]
__device__ float g_k[2][BATCH*NH*SEQ*HD];
__device__ float g_v[2][BATCH*NH*SEQ*HD];
__device__ float g_o[2][ROWS*E];               // attention out, head-concat layout
__device__ float g_M[2][E*E];                  // combined fusion matrices
__device__ float g_cb[E];                      // combined bias
__device__ float g_scores[ROWS];               // pooling logits
__device__ float g_fused[ROWS*E];              // fused features

// ---------------- GEMM tile: 128 rows x 64 cols per block, 256 threads ----------------
struct GemmSmem {
    float As[16][132];   // [kk][row]
    float Ws[16][68];    // [kk][col]
};

__device__ __forceinline__ void gemm_tile(
    GemmSmem& sm,
    const float* __restrict__ A, int lda, int row0,
    const float* __restrict__ W, int ldw, int wrow0,
    int Kdim, ull (&acc)[4][4], int tid)
{
    int tc = tid & 15, tr = tid >> 4;
    for (int k0 = 0; k0 < Kdim; k0 += 16) {
        #pragma unroll
        for (int p = 0; p < 8; p++) {          // A panel: 128x16
            int i = tid + p * 256;
            int kk = i & 15, r = i >> 4;
            int k = k0 + kk;
            sm.As[kk][r] = (k < Kdim) ? A[(size_t)(row0 + r) * lda + k] : 0.f;
        }
        #pragma unroll
        for (int p = 0; p < 4; p++) {          // W panel: 64x16
            int i = tid + p * 256;
            int kk = i & 15, c = i >> 4;
            int k = k0 + kk;
            sm.Ws[kk][c] = (k < Kdim) ? W[(size_t)(wrow0 + c) * ldw + k] : 0.f;
        }
        __syncthreads();
        #pragma unroll
        for (int kk = 0; kk < 16; kk++) {
            ulonglong2 a01 = *(const ulonglong2*)&sm.As[kk][8*tr];
            ulonglong2 a23 = *(const ulonglong2*)&sm.As[kk][8*tr + 4];
            float4 wv = *(const float4*)&sm.Ws[kk][4*tc];
            ull ap[4] = {a01.x, a01.y, a23.x, a23.y};
            ull w2[4] = {pk2(wv.x, wv.x), pk2(wv.y, wv.y), pk2(wv.z, wv.z), pk2(wv.w, wv.w)};
            #pragma unroll
            for (int p = 0; p < 4; p++)
                #pragma unroll
                for (int j = 0; j < 4; j++)
                    acc[p][j] = ffma2(ap[p], w2[j], acc[p][j]);
        }
        __syncthreads();
    }
}

__device__ __forceinline__ void unpack_acc(ull (&acc)[4][4], float (&o)[8][4]) {
    #pragma unroll
    for (int p = 0; p < 4; p++)
        #pragma unroll
        for (int j = 0; j < 4; j++)
            upk2(acc[p][j], o[2*p][j], o[2*p+1][j]);
}

// ---------------- combine_w (blocks 0..15) + proj (blocks 16..143) ----------------
__global__ __launch_bounds__(256) void combine_proj_kernel(
    const float* __restrict__ x,
    const float* __restrict__ pw, const float* __restrict__ pb,
    const float* __restrict__ fw, const float* __restrict__ fb,
    const float* __restrict__ low, const float* __restrict__ lob,
    const float* __restrict__ gow, const float* __restrict__ gob)
{
    __shared__ GemmSmem sm;
    int tid = threadIdx.x;
    int blk = blockIdx.x;
    if (blk < 16) {
        int idx = blk * 256 + tid;             // 0..4095
        int e = idx >> 6, f = idx & 63;
        float a = 0.f, b = 0.f;
        #pragma unroll 4
        for (int g = 0; g < E; g++) {
            a = fmaf(fw[e*2*E + g],     low[g*E + f], a);
            b = fmaf(fw[e*2*E + E + g], gow[g*E + f], b);
        }
        g_M[0][idx] = a;
        g_M[1][idx] = b;
        if (idx < E) {
            float c = fb[idx];
            for (int g = 0; g < E; g++) {
                c = fmaf(fw[idx*2*E + g], lob[g], c);
                c = fmaf(fw[idx*2*E + E + g], gob[g], c);
            }
            g_cb[idx] = c;
        }
        return;
    }
    int row0 = (blk - 16) * 128;
    ull acc[4][4] = {};
    gemm_tile(sm, x, IN_DIM, row0, pw, IN_DIM, 0, IN_DIM, acc, tid);
    int tc = tid & 15, tr = tid >> 4;
    float o[8][4];
    unpack_acc(acc, o);
    float4 bias = *(const float4*)&pb[4*tc];
    #pragma unroll
    for (int i = 0; i < 8; i++) {
        int row = row0 + 8*tr + i;
        float4 v = {o[i][0] + bias.x, o[i][1] + bias.y, o[i][2] + bias.z, o[i][3] + bias.w};
        *(float4*)&g_xp[(size_t)row*E + 4*tc] = v;
    }
}

// ---------------- QKV projection for BOTH attentions in one launch ----------------
__global__ __launch_bounds__(256) void qkv_kernel(const float* __restrict__ loc_w,
                           const float* __restrict__ loc_b,
                           const float* __restrict__ glb_w,
                           const float* __restrict__ glb_b) {
    __shared__ GemmSmem sm;
    int tid = threadIdx.x;
    int row0 = blockIdx.x * 128;
    int y = blockIdx.y;          // 0..5
    int attn = y / 3, which = y % 3;
    const float* w    = attn ? glb_w : loc_w;
    const float* bias = attn ? glb_b : loc_b;
    ull acc[4][4] = {};
    gemm_tile(sm, g_xp, E, row0, w, E, which*64, E, acc, tid);
    int tc = tid & 15, tr = tid >> 4;
    float o[8][4];
    unpack_acc(acc, o);
    float* outp = (which == 0) ? g_q[attn] : (which == 1) ? g_k[attn] : g_v[attn];
    int c = 4*tc;
    int h = c >> 3, dd = c & 7;
    float4 bv = *(const float4*)&bias[which*64 + c];
    #pragma unroll
    for (int i = 0; i < 8; i++) {
        int row = row0 + 8*tr + i;
        int b = row >> 10, s = row & 1023;
        float4 v = {o[i][0] + bv.x, o[i][1] + bv.y, o[i][2] + bv.z, o[i][3] + bv.w};
        *(float4*)&outp[(((size_t)(b*NH + h))*SEQ + s)*HD + dd] = v;
    }
}

// ---------------- both attentions in one launch ----------------
// blocks [0,512):  local,  block = (bh, 256-query chunk), K/V tile in smem
// blocks [512,1024): sparse, block = (bh, 256-query chunk), K/V (j%3==0) in smem
__global__ __launch_bounds__(256) void attn_kernel() {
    __shared__ union {
        struct { float Ks[NKEYS][8]; float Vs[NKEYS][8]; } sp;   // 21.9 KB
        struct { ull K2[4][272]; ull V2[4][272]; } loc;           // 17.4 KB
    } u;
    int blk = blockIdx.x;
    int tid = threadIdx.x;
    if (blk < 512) {
        // ---- local path ----
        int bh = blk >> 2;
        int chunk0 = (blk & 3) * 256;
        const float* kb = g_k[0] + (size_t)bh * SEQ * HD;
        const float* vb = g_v[0] + (size_t)bh * SEQ * HD;
        // stage rows [chunk0-5, chunk0+260] as packed dim-pairs; OOR -> 0
        for (int i = tid; i < 266*4; i += 256) {
            int dp = i & 3, r = i >> 2;
            int row = chunk0 - 5 + r;
            ull kv = 0, vv = 0;
            if (row >= 0 && row < SEQ) {
                kv = *(const ull*)(kb + (size_t)row*HD + 2*dp);
                vv = *(const ull*)(vb + (size_t)row*HD + 2*dp);
            }
            u.loc.K2[dp][r] = kv;
            u.loc.V2[dp][r] = vv;
        }
        __syncthreads();
        int s = chunk0 + tid;
        const ull* qp = (const ull*)(g_q[0] + ((size_t)bh * SEQ + s) * HD);
        ull q0 = qp[0], q1 = qp[1], q2 = qp[2], q3 = qp[3];
        float l = 0.f;
        ull acc[4] = {0,0,0,0};
        int j0 = s - WIN;
        #pragma unroll
        for (int jj = 0; jj < 2*WIN+1; jj++) {
            int r = tid + jj;
            ull d2 = ffma2(q0, u.loc.K2[0][r],
                     ffma2(q1, u.loc.K2[1][r],
                     ffma2(q2, u.loc.K2[2][r],
                     fmul2(q3, u.loc.K2[3][r]))));
            float dl, dh; upk2(d2, dl, dh);
            unsigned jg = (unsigned)(j0 + jj);
            float p = (jg < SEQ) ? __expf((dl + dh) * SCALE) : 0.f;
            l += p;
            ull pp = pk2(p, p);
            acc[0] = ffma2(pp, u.loc.V2[0][r], acc[0]);
            acc[1] = ffma2(pp, u.loc.V2[1][r], acc[1]);
            acc[2] = ffma2(pp, u.loc.V2[2][r], acc[2]);
            acc[3] = ffma2(pp, u.loc.V2[3][r], acc[3]);
        }
        float inv = 1.f / l;
        float oo[8];
        upk2(acc[0], oo[0], oo[1]); upk2(acc[1], oo[2], oo[3]);
        upk2(acc[2], oo[4], oo[5]); upk2(acc[3], oo[6], oo[7]);
        int b = bh >> 3, h = bh & 7;
        float* op = g_o[0] + ((size_t)(b*SEQ + s))*E + h*HD;
        float4 o0 = {oo[0]*inv, oo[1]*inv, oo[2]*inv, oo[3]*inv};
        float4 o1 = {oo[4]*inv, oo[5]*inv, oo[6]*inv, oo[7]*inv};
        *(float4*)op = o0;
        *(float4*)(op + 4) = o1;
    } else {
        // ---- sparse path ----
        int bb = blk - 512;
        int bh = bb >> 2;
        int s  = (bb & 3) * 256 + tid;
        const float* kb = g_k[1] + (size_t)bh * SEQ * HD;
        const float* vb = g_v[1] + (size_t)bh * SEQ * HD;
        for (int i = tid; i < NKEYS*8; i += 256) {
            int kk = i >> 3, dd = i & 7;
            u.sp.Ks[kk][dd] = kb[kk*24 + dd];     // key row 3*kk
            u.sp.Vs[kk][dd] = vb[kk*24 + dd];
        }
        __syncthreads();
        const ull* qp = (const ull*)(g_q[1] + ((size_t)bh * SEQ + s) * HD);
        ull q0 = qp[0], q1 = qp[1], q2 = qp[2], q3 = qp[3];
        float l = 0.f;
        ull acc[4] = {0,0,0,0};
        #pragma unroll 2
        for (int kk = 0; kk < NKEYS; kk++) {
            const ull* kp = (const ull*)&u.sp.Ks[kk][0];
            ull d2 = ffma2(q0, kp[0], ffma2(q1, kp[1], ffma2(q2, kp[2], fmul2(q3, kp[3]))));
            float dl, dh; upk2(d2, dl, dh);
            float p = __expf((dl + dh) * SCALE);
            l += p;
            ull pp = pk2(p, p);
            const ull* vp = (const ull*)&u.sp.Vs[kk][0];
            acc[0] = ffma2(pp, vp[0], acc[0]);
            acc[1] = ffma2(pp, vp[1], acc[1]);
            acc[2] = ffma2(pp, vp[2], acc[2]);
            acc[3] = ffma2(pp, vp[3], acc[3]);
        }
        if (s % 3) {                               // diagonal key not in the j%3 set
            const ull* kp = (const ull*)(kb + (size_t)s * HD);
            ull d2 = ffma2(q0, kp[0], ffma2(q1, kp[1], ffma2(q2, kp[2], fmul2(q3, kp[3]))));
            float dl, dh; upk2(d2, dl, dh);
            float p = __expf((dl + dh) * SCALE);
            l += p;
            ull pp = pk2(p, p);
            const ull* vp = (const ull*)(vb + (size_t)s * HD);
            acc[0] = ffma2(pp, vp[0], acc[0]);
            acc[1] = ffma2(pp, vp[1], acc[1]);
            acc[2] = ffma2(pp, vp[2], acc[2]);
            acc[3] = ffma2(pp, vp[3], acc[3]);
        }
        float inv = 1.f / l;
        float oo[8];
        upk2(acc[0], oo[0], oo[1]); upk2(acc[1], oo[2], oo[3]);
        upk2(acc[2], oo[4], oo[5]); upk2(acc[3], oo[6], oo[7]);
        int b = bh >> 3, h = bh & 7;
        float* op = g_o[1] + ((size_t)(b*SEQ + s))*E + h*HD;
        float4 o0 = {oo[0]*inv, oo[1]*inv, oo[2]*inv, oo[3]*inv};
        float4 o1 = {oo[4]*inv, oo[5]*inv, oo[6]*inv, oo[7]*inv};
        *(float4*)op = o0;
        *(float4*)(op + 4) = o1;
    }
}

// ---------------- fused = o_loc @ M_loc^T + o_glob @ M_glob^T + cb ----------------
__global__ __launch_bounds__(256) void fused_kernel() {
    __shared__ GemmSmem sm;
    int tid = threadIdx.x;
    int row0 = blockIdx.x * 128;
    ull acc[4][4] = {};
    gemm_tile(sm, g_o[0], E, row0, g_M[0], E, 0, E, acc, tid);
    gemm_tile(sm, g_o[1], E, row0, g_M[1], E, 0, E, acc, tid);
    int tc = tid & 15, tr = tid >> 4;
    float o[8][4];
    unpack_acc(acc, o);
    float4 bias = *(const float4*)&g_cb[4*tc];
    #pragma unroll
    for (int i = 0; i < 8; i++) {
        int row = row0 + 8*tr + i;
        float4 v = {o[i][0] + bias.x, o[i][1] + bias.y, o[i][2] + bias.z, o[i][3] + bias.w};
        *(float4*)&g_fused[(size_t)row*E + 4*tc] = v;
    }
}

// ---------------- pooling logits: tanh(fused@w1^T+b1)@w2^T+b2 ----------------
__global__ void pool_score_kernel(const float* __restrict__ w1,
                                  const float* __restrict__ b1,
                                  const float* __restrict__ w2,
                                  const float* __restrict__ b2) {
    __shared__ float w1s[32][65];
    __shared__ float w2s[32], b1s[32];
    int tid = threadIdx.x;
    for (int i = tid; i < 32*64; i += blockDim.x)
        w1s[i >> 6][i & 63] = w1[i];
    if (tid < 32) { w2s[tid] = w2[tid]; b1s[tid] = b1[tid]; }
    __syncthreads();
    int warp = tid >> 5, lane = tid & 31;
    int row = blockIdx.x * 8 + warp;
    const float* fr = g_fused + (size_t)row * E;
    float f0 = fr[lane], f1 = fr[lane + 32];
    float h = 0.f;
    #pragma unroll
    for (int e = 0; e < 32; e++) {
        float v = __shfl_sync(0xffffffffu, f0, e);
        h = fmaf(v, w1s[lane][e], h);
    }
    #pragma unroll
    for (int e = 0; e < 32; e++) {
        float v = __shfl_sync(0xffffffffu, f1, e);
        h = fmaf(v, w1s[lane][e + 32], h);
    }
    h = tanhf(h + b1s[lane]);
    float p = h * w2s[lane];
    #pragma unroll
    for (int off = 16; off; off >>= 1)
        p += __shfl_xor_sync(0xffffffffu, p, off);
    if (lane == 0) g_scores[row] = p + b2[0];
}

// ---------------- softmax over seq + weighted sum -> out[b][e] ----------------
__global__ void pool_out_kernel(float* __restrict__ out) {
    int b = blockIdx.x;
    int tid = threadIdx.x;  // 256
    __shared__ float ws[SEQ];
    __shared__ float red[8];
    __shared__ float s_max, s_sum;
    __shared__ float part[4][64];
    const float* sc = g_scores + (size_t)b * SEQ;
    float m = -1e30f;
    for (int i = tid; i < SEQ; i += 256) m = fmaxf(m, sc[i]);
    #pragma unroll
    for (int off = 16; off; off >>= 1) m = fmaxf(m, __shfl_xor_sync(0xffffffffu, m, off));
    if ((tid & 31) == 0) red[tid >> 5] = m;
    __syncthreads();
    if (tid == 0) {
        float mm = red[0];
        for (int i = 1; i < 8; i++) mm = fmaxf(mm, red[i]);
        s_max = mm;
    }
    __syncthreads();
    float mm = s_max;
    float lsum = 0.f;
    for (int i = tid; i < SEQ; i += 256) {
        float e = __expf(sc[i] - mm);
        ws[i] = e;
        lsum += e;
    }
    #pragma unroll
    for (int off = 16; off; off >>= 1) lsum += __shfl_xor_sync(0xffffffffu, lsum, off);
    __syncthreads();
    if ((tid & 31) == 0) red[tid >> 5] = lsum;
    __syncthreads();
    if (tid == 0) {
        float ss = 0.f;
        for (int i = 0; i < 8; i++) ss += red[i];
        s_sum = ss;
    }
    __syncthreads();
    int e = tid & 63, g = tid >> 6;
    const float* fb = g_fused + (size_t)b * SEQ * E;
    float a = 0.f;
    for (int s = g*256; s < g*256 + 256; s++)
        a = fmaf(ws[s], fb[(size_t)s*E + e], a);
    part[g][e] = a;
    __syncthreads();
    if (tid < 64)
        out[b*64 + tid] = (part[0][tid] + part[1][tid] + part[2][tid] + part[3][tid]) / s_sum;
}

// ---------------- launch ----------------
extern "C" void kernel_launch(void* const* d_in, const int* in_sizes, int n_in,
                              void* d_out, int out_size) {
    const float* x        = (const float*)d_in[0];
    const float* proj_w   = (const float*)d_in[1];
    const float* proj_b   = (const float*)d_in[2];
    const float* loc_in_w = (const float*)d_in[3];
    const float* loc_in_b = (const float*)d_in[4];
    const float* loc_out_w= (const float*)d_in[5];
    const float* loc_out_b= (const float*)d_in[6];
    const float* glb_in_w = (const float*)d_in[7];
    const float* glb_in_b = (const float*)d_in[8];
    const float* glb_out_w= (const float*)d_in[9];
    const float* glb_out_b= (const float*)d_in[10];
    const float* fusion_w = (const float*)d_in[11];
    const float* fusion_b = (const float*)d_in[12];
    const float* pool_w1  = (const float*)d_in[13];
    const float* pool_b1  = (const float*)d_in[14];
    const float* pool_w2  = (const float*)d_in[15];
    const float* pool_b2  = (const float*)d_in[16];
    float* out = (float*)d_out;

    combine_proj_kernel<<<16 + ROWS/128, 256>>>(x, proj_w, proj_b,
                                                fusion_w, fusion_b,
                                                loc_out_w, loc_out_b,
                                                glb_out_w, glb_out_b);
    qkv_kernel<<<dim3(ROWS/128, 6), 256>>>(loc_in_w, loc_in_b, glb_in_w, glb_in_b);
    attn_kernel<<<1024, 256>>>();
    fused_kernel<<<ROWS/128, 256>>>();
    pool_score_kernel<<<ROWS/8, 256>>>(pool_w1, pool_b1, pool_w2, pool_b2);
    pool_out_kernel<<<BATCH, 256>>>(out);
}